// round 17
// baseline (speedup 1.0000x reference)
#include <cuda_runtime.h>

#define NUM_SEG 512
#define D4 16          // float4 chunks per row (D=64)
#define CPS 8          // chunks per segment
#define TPB 512
#define NWARP (TPB / 32)   // 16
#define RGN (TPB / D4)     // 32 row groups

// Device scratch (reset/overwritten every launch -> deterministic).
__device__ float4 g_psum[NUM_SEG * CPS * D4];
__device__ float  g_psq [NUM_SEG * CPS];
__device__ int    g_cnt [NUM_SEG];

__device__ __forceinline__ int lower_bound_i32(const int* __restrict__ a, int n, int v) {
    int lo = 0, hi = n;
    while (lo < hi) {
        int mid = (lo + hi) >> 1;
        if (a[mid] < v) lo = mid + 1; else hi = mid;
    }
    return lo;
}

__global__ __launch_bounds__(NUM_SEG) void k_init() {
    g_cnt[threadIdx.x] = 0;
}

__global__ __launch_bounds__(TPB) void k_fused(
    const float4* __restrict__ x4,   // [N,16]
    const int* __restrict__ batch,   // [N] sorted int32
    float4* __restrict__ out4,
    int N)
{
    const int bid = blockIdx.x;      // 0 .. 4095
    const int s   = bid >> 3;        // segment 0..511
    const int q   = bid & 7;         // chunk 0..7
    const int tid = threadIdx.x;
    const int lane = tid & 31;
    const int wid  = tid >> 5;       // 0..15
    const int c4 = tid & (D4 - 1);   // column chunk 0..15
    const int rg = tid >> 4;         // row group 0..31

    __shared__ float4 sh_wsum[NWARP * D4];   // 4 KB
    __shared__ float  sh_wsq[NWARP];
    __shared__ float4 sh_fin[CPS * D4];      // 2 KB finalize staging
    __shared__ float4 sh_mean[D4];
    __shared__ float  sh_msq[D4];
    __shared__ float  sh_inv;
    __shared__ int    sh_b[2];

    if (tid == 0)  sh_b[0] = lower_bound_i32(batch, N, s);
    if (tid == 32) sh_b[1] = lower_bound_i32(batch, N, s + 1);
    __syncthreads();
    const int lo = sh_b[0], len = sh_b[1] - sh_b[0];
    const int qlo = lo + ((len * q) >> 3);
    const int qhi = lo + ((len * (q + 1)) >> 3);
    const int nrows = qhi - qlo;

    // ---- Phase A: pure read stream (default policy -> chunk stays in L2) ----
    const unsigned FULL = 0xffffffffu;
    float4 sum4 = make_float4(0.f, 0.f, 0.f, 0.f);
    float  sq   = 0.f;
    int rr = rg;
    for (; rr + 3 * RGN < nrows; rr += 4 * RGN) {
        float4 v0 = x4[(size_t)(qlo + rr) * D4 + c4];
        float4 v1 = x4[(size_t)(qlo + rr + RGN) * D4 + c4];
        float4 v2 = x4[(size_t)(qlo + rr + 2 * RGN) * D4 + c4];
        float4 v3 = x4[(size_t)(qlo + rr + 3 * RGN) * D4 + c4];
        sum4.x += (v0.x + v1.x) + (v2.x + v3.x);
        sum4.y += (v0.y + v1.y) + (v2.y + v3.y);
        sum4.z += (v0.z + v1.z) + (v2.z + v3.z);
        sum4.w += (v0.w + v1.w) + (v2.w + v3.w);
        sq += v0.x * v0.x + v0.y * v0.y + v0.z * v0.z + v0.w * v0.w;
        sq += v1.x * v1.x + v1.y * v1.y + v1.z * v1.z + v1.w * v1.w;
        sq += v2.x * v2.x + v2.y * v2.y + v2.z * v2.z + v2.w * v2.w;
        sq += v3.x * v3.x + v3.y * v3.y + v3.z * v3.z + v3.w * v3.w;
    }
    for (; rr < nrows; rr += RGN) {
        float4 v = x4[(size_t)(qlo + rr) * D4 + c4];
        sum4.x += v.x; sum4.y += v.y; sum4.z += v.z; sum4.w += v.w;
        sq += v.x * v.x + v.y * v.y + v.z * v.z + v.w * v.w;
    }

    // warp reduce: lane+16 shares c4
    sum4.x += __shfl_down_sync(FULL, sum4.x, 16);
    sum4.y += __shfl_down_sync(FULL, sum4.y, 16);
    sum4.z += __shfl_down_sync(FULL, sum4.z, 16);
    sum4.w += __shfl_down_sync(FULL, sum4.w, 16);
#pragma unroll
    for (int off = 16; off >= 1; off >>= 1)
        sq += __shfl_down_sync(FULL, sq, off);
    if (lane < D4) sh_wsum[wid * D4 + lane] = sum4;
    if (lane == 0) sh_wsq[wid] = sq;
    __syncthreads();

    if (tid < D4) {
        float4 t = sh_wsum[tid];
#pragma unroll
        for (int w = 1; w < NWARP; w++) {
            float4 b = sh_wsum[w * D4 + tid];
            t.x += b.x; t.y += b.y; t.z += b.z; t.w += b.w;
        }
        g_psum[bid * D4 + tid] = t;
    }
    if (tid == 32) {
        float t = 0.f;
#pragma unroll
        for (int w = 0; w < NWARP; w++) t += sh_wsq[w];
        g_psq[bid] = t;
    }
    __threadfence();
    __syncthreads();
    if (tid == 0) {
        atomicAdd(&g_cnt[s], 1);
        while (((volatile int*)g_cnt)[s] < CPS) __nanosleep(64);
    }
    __syncthreads();
    __threadfence();

    // ---- Redundant decentralized finalize (every block, in smem) ----
    if (tid < CPS * D4) {            // 128 threads: qq = tid>>4, c4 = tid&15
        sh_fin[tid] = __ldcg(&g_psum[s * (CPS * D4) + tid]);
    }
    __syncthreads();
    const float invc = 1.f / (float)max(len, 1);
    if (tid < D4) {
        float4 t = sh_fin[tid];
#pragma unroll
        for (int qq = 1; qq < CPS; qq++) {
            float4 b = sh_fin[qq * D4 + tid];
            t.x += b.x; t.y += b.y; t.z += b.z; t.w += b.w;
        }
        float4 m = make_float4(t.x * invc, t.y * invc, t.z * invc, t.w * invc);
        sh_mean[tid] = m;
        sh_msq[tid] = m.x * m.x + m.y * m.y + m.z * m.z + m.w * m.w;
    }
    __syncthreads();
    if (tid == 0) {
        float sq_tot = 0.f, msq = 0.f;
#pragma unroll
        for (int i = 0; i < CPS; i++) sq_tot += __ldcg(&g_psq[s * CPS + i]);
#pragma unroll
        for (int i = 0; i < D4; i++) msq += sh_msq[i];
        // segment_mean(|x-m|^2) = segment_mean(|x|^2) - |m|^2
        float var = sq_tot * invc - msq;
        sh_inv = rsqrtf(var);
    }
    __syncthreads();

    // ---- Phase B: re-read own chunk (L2-resident), streaming output ----
    const float4 m  = sh_mean[c4];
    const float  gi = sh_inv;
    rr = rg;
    for (; rr + RGN < nrows; rr += 2 * RGN) {
        const size_t i0 = (size_t)(qlo + rr) * D4 + c4;
        const size_t i1 = (size_t)(qlo + rr + RGN) * D4 + c4;
        float4 v0 = __ldcs(&x4[i0]);   // L2 hit; evict after use
        float4 v1 = __ldcs(&x4[i1]);
        float4 o0, o1;
        o0.x = (v0.x - m.x) * gi; o0.y = (v0.y - m.y) * gi;
        o0.z = (v0.z - m.z) * gi; o0.w = (v0.w - m.w) * gi;
        o1.x = (v1.x - m.x) * gi; o1.y = (v1.y - m.y) * gi;
        o1.z = (v1.z - m.z) * gi; o1.w = (v1.w - m.w) * gi;
        __stcs(&out4[i0], o0);
        __stcs(&out4[i1], o1);
    }
    if (rr < nrows) {
        const size_t i0 = (size_t)(qlo + rr) * D4 + c4;
        float4 v0 = __ldcs(&x4[i0]);
        float4 o0;
        o0.x = (v0.x - m.x) * gi; o0.y = (v0.y - m.y) * gi;
        o0.z = (v0.z - m.z) * gi; o0.w = (v0.w - m.w) * gi;
        __stcs(&out4[i0], o0);
    }
}

extern "C" void kernel_launch(void* const* d_in, const int* in_sizes, int n_in,
                              void* d_out, int out_size)
{
    const float* x     = (const float*)d_in[0];   // [N, 64]
    const int*   batch = (const int*)d_in[1];     // [N], sorted int32
    float*       out   = (float*)d_out;
    const int N = in_sizes[1];

    k_init<<<1, NUM_SEG>>>();
    k_fused<<<NUM_SEG * CPS, TPB>>>((const float4*)x, batch, (float4*)out, N);
}